// round 9
// baseline (speedup 1.0000x reference)
#include <cuda_runtime.h>
#include <cuda_fp16.h>
#include <cstdint>

#define MAX_N 100000
#define MAX_E 1600000
#define F 128
#define SCAN_CHUNK 512
#define MAX_BLK ((MAX_N + SCAN_CHUNK - 1) / SCAN_CHUNK)
#define PITCH 132   // 128 + 4 pad: conflict-free mma A-frag loads

// Scratch (__device__ globals; no allocations allowed).
// g_cnt relies on zero-init at load; k_agg re-zeroes it each run.
__device__ __half2 g_h16[(size_t)MAX_N * (F / 2)];  // (x@W)*dinv[row], fp16
__device__ float g_dinv[MAX_N];
__device__ int   g_cnt[MAX_N];
__device__ int   g_start[MAX_N];
__device__ int   g_cursor[MAX_N];
__device__ int   g_esrc[MAX_E];
__device__ int   g_bsum[MAX_BLK];
__device__ float4 g_wfrag[16 * 8 * 32];     // frag-ordered tf32 W (64KB)

// ---------------------------------------------------------------------------
__global__ void k_hist(const int* __restrict__ dst, int e) {
    int i = blockIdx.x * blockDim.x + threadIdx.x;
    if (i < e) atomicAdd(&g_cnt[dst[i]], 1);
}

__global__ void k_scan1(int n) {
    __shared__ int wsum[16];
    int b = blockIdx.x;
    int i = b * SCAN_CHUNK + threadIdx.x;
    int v = (i < n) ? g_cnt[i] : 0;
    for (int o = 16; o > 0; o >>= 1) v += __shfl_down_sync(~0u, v, o);
    int lane = threadIdx.x & 31, wid = threadIdx.x >> 5;
    if (lane == 0) wsum[wid] = v;
    __syncthreads();
    if (wid == 0) {
        int s = (lane < (SCAN_CHUNK / 32)) ? wsum[lane] : 0;
        for (int o = 16; o > 0; o >>= 1) s += __shfl_down_sync(~0u, s, o);
        if (lane == 0) g_bsum[b] = s;
    }
}

// fused: every block re-scans all block sums locally, then does its own chunk
__global__ void k_scan3(int n, int nblk) {
    __shared__ int wsum[16];
    __shared__ int sh_off;
    int b = blockIdx.x;
    int t = threadIdx.x;
    int lane = t & 31, wid = t >> 5;

    {
        int v = (t < nblk) ? g_bsum[t] : 0;
        int x = v;
        for (int o = 1; o < 32; o <<= 1) {
            int y = __shfl_up_sync(~0u, x, o);
            if (lane >= o) x += y;
        }
        if (lane == 31) wsum[wid] = x;
        __syncthreads();
        if (wid == 0) {
            int w = (lane < 16) ? wsum[lane] : 0;
            for (int o = 1; o < 16; o <<= 1) {
                int y = __shfl_up_sync(~0u, w, o);
                if (lane >= o) w += y;
            }
            if (lane < 16) wsum[lane] = w;
        }
        __syncthreads();
        int excl = x - v + (wid ? wsum[wid - 1] : 0);
        if (t == b) sh_off = excl;
        __syncthreads();
    }

    int i = b * SCAN_CHUNK + t;
    int v = (i < n) ? g_cnt[i] : 0;
    int x = v;
    for (int o = 1; o < 32; o <<= 1) {
        int y = __shfl_up_sync(~0u, x, o);
        if (lane >= o) x += y;
    }
    if (lane == 31) wsum[wid] = x;
    __syncthreads();
    if (wid == 0) {
        int w = (lane < 16) ? wsum[lane] : 0;
        for (int o = 1; o < 16; o <<= 1) {
            int y = __shfl_up_sync(~0u, w, o);
            if (lane >= o) w += y;
        }
        if (lane < 16) wsum[lane] = w;
    }
    __syncthreads();
    int excl = x - v + (wid ? wsum[wid - 1] : 0);
    if (i < n) {
        int s = excl + sh_off;
        g_start[i] = s;
        g_cursor[i] = s;
    }
}

__global__ void k_fill(const int* __restrict__ src, const int* __restrict__ dst,
                       int e) {
    int i = blockIdx.x * blockDim.x + threadIdx.x;
    if (i < e) {
        int p = atomicAdd(&g_cursor[dst[i]], 1);
        g_esrc[p] = src[i];
    }
}

// ---------------------------------------------------------------------------
__device__ __forceinline__ unsigned cvt_tf32(float f) {
    unsigned u;
    asm("cvt.rna.tf32.f32 %0, %1;" : "=r"(u) : "f"(f));
    return u;
}

// One-time: convert W into fragment-ordered tf32.
__global__ void k_wprep(const float* __restrict__ W) {
    int i = blockIdx.x * blockDim.x + threadIdx.x;
    if (i >= 16 * 8 * 32) return;
    int lane = i & 31;
    int ktp = (i >> 5) & 7;
    int nt = i >> 8;
    int g = lane >> 2, t = lane & 3;
    int nc = nt * 8 + g;
    int k0 = ktp * 16 + t;
    float4 o;
    o.x = __uint_as_float(cvt_tf32(W[(k0)      * F + nc]));
    o.y = __uint_as_float(cvt_tf32(W[(k0 + 4)  * F + nc]));
    o.z = __uint_as_float(cvt_tf32(W[(k0 + 8)  * F + nc]));
    o.w = __uint_as_float(cvt_tf32(W[(k0 + 12) * F + nc]));
    g_wfrag[i] = o;
}

// GEMM via HMMA tf32: g_h16 = (x @ W) * dinv[row], fp16 out. B frags from
// g_wfrag (broadcast LDG.128). Two interleaved nt-tiles per iter (2x MMA ILP).
__global__ __launch_bounds__(256, 2) void k_gemm(const float* __restrict__ x,
                                                 int n) {
    extern __shared__ float xs[];     // xs[r*PITCH + k] = tf32(x[row0+r][k])

    const int tid = threadIdx.x;
    const int row0 = blockIdx.x * 128;
    for (int i = tid; i < 128 * 32; i += 256) {
        int r = i >> 5, k4 = i & 31;
        float4 v = make_float4(0.f, 0.f, 0.f, 0.f);
        if (row0 + r < n) v = ((const float4*)x)[(long long)(row0 + r) * 32 + k4];
        v.x = __uint_as_float(cvt_tf32(v.x));
        v.y = __uint_as_float(cvt_tf32(v.y));
        v.z = __uint_as_float(cvt_tf32(v.z));
        v.w = __uint_as_float(cvt_tf32(v.w));
        *(float4*)&xs[r * PITCH + k4 * 4] = v;
    }
    if (tid < 128 && row0 + tid < n)
        g_dinv[row0 + tid] = rsqrtf((float)(g_cnt[row0 + tid] + 1));
    __syncthreads();

    const int warp = tid >> 5, lane = tid & 31;
    const int g = lane >> 2, t = lane & 3;
    const int rbase = warp * 16;

    unsigned a[16][4];
#pragma unroll
    for (int kt = 0; kt < 16; kt++) {
        a[kt][0] = __float_as_uint(xs[(rbase + g) * PITCH + kt * 8 + t]);
        a[kt][1] = __float_as_uint(xs[(rbase + g + 8) * PITCH + kt * 8 + t]);
        a[kt][2] = __float_as_uint(xs[(rbase + g) * PITCH + kt * 8 + t + 4]);
        a[kt][3] = __float_as_uint(xs[(rbase + g + 8) * PITCH + kt * 8 + t + 4]);
    }

    const int row_g = row0 + rbase + g;
    float sr  = (row_g < n)     ? rsqrtf((float)(g_cnt[row_g] + 1))     : 0.f;
    float sr8 = (row_g + 8 < n) ? rsqrtf((float)(g_cnt[row_g + 8] + 1)) : 0.f;

    const float4* wf = g_wfrag;
#pragma unroll 2
    for (int np = 0; np < 8; np++) {
        const int ntA = 2 * np, ntB = 2 * np + 1;
        float dA0 = 0.f, dA1 = 0.f, dA2 = 0.f, dA3 = 0.f;
        float dB0 = 0.f, dB1 = 0.f, dB2 = 0.f, dB3 = 0.f;
#pragma unroll
        for (int ktp = 0; ktp < 8; ktp++) {
            float4 bfA = wf[(ntA * 8 + ktp) * 32 + lane];
            float4 bfB = wf[(ntB * 8 + ktp) * 32 + lane];
            const unsigned* aa0 = a[2 * ktp];
            const unsigned* aa1 = a[2 * ktp + 1];
            asm volatile(
                "mma.sync.aligned.m16n8k8.row.col.f32.tf32.tf32.f32 "
                "{%0,%1,%2,%3}, {%4,%5,%6,%7}, {%8,%9}, {%0,%1,%2,%3};"
                : "+f"(dA0), "+f"(dA1), "+f"(dA2), "+f"(dA3)
                : "r"(aa0[0]), "r"(aa0[1]), "r"(aa0[2]), "r"(aa0[3]),
                  "r"(__float_as_uint(bfA.x)), "r"(__float_as_uint(bfA.y)));
            asm volatile(
                "mma.sync.aligned.m16n8k8.row.col.f32.tf32.tf32.f32 "
                "{%0,%1,%2,%3}, {%4,%5,%6,%7}, {%8,%9}, {%0,%1,%2,%3};"
                : "+f"(dB0), "+f"(dB1), "+f"(dB2), "+f"(dB3)
                : "r"(aa0[0]), "r"(aa0[1]), "r"(aa0[2]), "r"(aa0[3]),
                  "r"(__float_as_uint(bfB.x)), "r"(__float_as_uint(bfB.y)));
            asm volatile(
                "mma.sync.aligned.m16n8k8.row.col.f32.tf32.tf32.f32 "
                "{%0,%1,%2,%3}, {%4,%5,%6,%7}, {%8,%9}, {%0,%1,%2,%3};"
                : "+f"(dA0), "+f"(dA1), "+f"(dA2), "+f"(dA3)
                : "r"(aa1[0]), "r"(aa1[1]), "r"(aa1[2]), "r"(aa1[3]),
                  "r"(__float_as_uint(bfA.z)), "r"(__float_as_uint(bfA.w)));
            asm volatile(
                "mma.sync.aligned.m16n8k8.row.col.f32.tf32.tf32.f32 "
                "{%0,%1,%2,%3}, {%4,%5,%6,%7}, {%8,%9}, {%0,%1,%2,%3};"
                : "+f"(dB0), "+f"(dB1), "+f"(dB2), "+f"(dB3)
                : "r"(aa1[0]), "r"(aa1[1]), "r"(aa1[2]), "r"(aa1[3]),
                  "r"(__float_as_uint(bfB.z)), "r"(__float_as_uint(bfB.w)));
        }
        if (row_g < n) {
            g_h16[(size_t)row_g * 64 + ntA * 4 + t] =
                __floats2half2_rn(dA0 * sr, dA1 * sr);
            g_h16[(size_t)row_g * 64 + ntB * 4 + t] =
                __floats2half2_rn(dB0 * sr, dB1 * sr);
        }
        if (row_g + 8 < n) {
            g_h16[(size_t)(row_g + 8) * 64 + ntA * 4 + t] =
                __floats2half2_rn(dA2 * sr8, dA3 * sr8);
            g_h16[(size_t)(row_g + 8) * 64 + ntB * 4 + t] =
                __floats2half2_rn(dB2 * sr8, dB3 * sr8);
        }
    }
}

// ---------------------------------------------------------------------------
// Aggregate: one warp per dst node; uint2/lane fp16 gathers (R5 structure).
// Also re-zeroes g_cnt for the next graph replay.
__global__ __launch_bounds__(256) void k_agg(const float* __restrict__ bias,
                                             float* __restrict__ out, int n) {
    int node = blockIdx.x * 8 + (threadIdx.x >> 5);
    if (node >= n) return;
    int lane = threadIdx.x & 31;

    const uint2* h = (const uint2*)g_h16;  // 4 halfs / lane / row
    float dd = g_dinv[node];

    float4 acc;
    {
        uint2 sv = h[(size_t)node * 32 + lane];  // self-loop message
        float2 f0 = __half22float2(*(__half2*)&sv.x);
        float2 f1 = __half22float2(*(__half2*)&sv.y);
        acc.x = f0.x; acc.y = f0.y; acc.z = f1.x; acc.w = f1.y;
    }

    int j = g_start[node];
    int cnt = g_cnt[node];
    int end = j + cnt;
    if (lane == 0) g_cnt[node] = 0;   // reset histogram for next replay

    for (; j + 3 < end; j += 4) {
        int s0 = g_esrc[j], s1 = g_esrc[j + 1];
        int s2 = g_esrc[j + 2], s3 = g_esrc[j + 3];
        uint2 v0 = h[(size_t)s0 * 32 + lane];
        uint2 v1 = h[(size_t)s1 * 32 + lane];
        uint2 v2 = h[(size_t)s2 * 32 + lane];
        uint2 v3 = h[(size_t)s3 * 32 + lane];
#pragma unroll
        for (int q = 0; q < 4; q++) {
            uint2 v = (q == 0) ? v0 : (q == 1) ? v1 : (q == 2) ? v2 : v3;
            float2 f0 = __half22float2(*(__half2*)&v.x);
            float2 f1 = __half22float2(*(__half2*)&v.y);
            acc.x += f0.x; acc.y += f0.y; acc.z += f1.x; acc.w += f1.y;
        }
    }
    for (; j < end; j++) {
        int s = g_esrc[j];
        uint2 v = h[(size_t)s * 32 + lane];
        float2 f0 = __half22float2(*(__half2*)&v.x);
        float2 f1 = __half22float2(*(__half2*)&v.y);
        acc.x += f0.x; acc.y += f0.y; acc.z += f1.x; acc.w += f1.y;
    }

    float4 bv = ((const float4*)bias)[lane];
    float4 o;
    o.x = acc.x * dd + bv.x;
    o.y = acc.y * dd + bv.y;
    o.z = acc.z * dd + bv.z;
    o.w = acc.w * dd + bv.w;
    ((float4*)out)[(size_t)node * 32 + lane] = o;
}

// ---------------------------------------------------------------------------
extern "C" void kernel_launch(void* const* d_in, const int* in_sizes, int n_in,
                              void* d_out, int out_size) {
    const float* x  = (const float*)d_in[0];
    const int*   ei = (const int*)d_in[1];
    const float* W  = (const float*)d_in[3];
    const float* b  = (const float*)d_in[4];
    float* out = (float*)d_out;

    int n = in_sizes[0] / F;
    int e = in_sizes[1] / 2;
    const int* src = ei;
    const int* dst = ei + e;

    int nblk = (n + SCAN_CHUNK - 1) / SCAN_CHUNK;

    static bool attr_done = false;
    int smem = 128 * PITCH * (int)sizeof(float);   // 67.6 KB
    if (!attr_done) {
        cudaFuncSetAttribute(k_gemm, cudaFuncAttributeMaxDynamicSharedMemorySize,
                             smem);
        attr_done = true;
    }

    k_hist <<<(e + 255) / 256, 256>>>(dst, e);             // 1 (g_cnt zeroed by prev agg / load)
    k_wprep<<<16, 256>>>(W);                               // 2
    k_scan1<<<nblk, SCAN_CHUNK>>>(n);                      // 3
    k_gemm <<<(n + 127) / 128, 256, smem>>>(x, n);         // 4  <- profiled slot
    k_scan3<<<nblk, SCAN_CHUNK>>>(n, nblk);                // 5
    k_fill <<<(e + 255) / 256, 256>>>(src, dst, e);        // 6
    k_agg  <<<(n + 7) / 8, 256>>>(b, out, n);              // 7
}

// round 10
// speedup vs baseline: 1.6188x; 1.6188x over previous
#include <cuda_runtime.h>
#include <cuda_fp16.h>
#include <cstdint>

#define MAX_N 100000
#define MAX_E 1600000
#define F 128
#define SCAN_CHUNK 512
#define MAX_BLK ((MAX_N + SCAN_CHUNK - 1) / SCAN_CHUNK)
#define PITCH 132   // 128 + 4 pad: conflict-free mma A-frag loads

// Scratch (__device__ globals; no allocations allowed)
__device__ float g_hs[(size_t)MAX_N * F];   // (x@W)*dinv[row], fp32 (51.2MB)
__device__ float g_dinv[MAX_N];
__device__ int   g_cnt[MAX_N];
__device__ int   g_start[MAX_N];
__device__ int   g_cursor[MAX_N];
__device__ int   g_esrc[MAX_E];
__device__ int   g_bsum[MAX_BLK];
__device__ float4 g_wfrag[16 * 8 * 32];     // frag-ordered tf32 W (64KB)

// ---------------------------------------------------------------------------
__global__ void k_zero(int n) {
    int i = blockIdx.x * blockDim.x + threadIdx.x;
    if (i < n) g_cnt[i] = 0;
}

__global__ void k_hist(const int* __restrict__ dst, int e) {
    int i = blockIdx.x * blockDim.x + threadIdx.x;
    if (i < e) atomicAdd(&g_cnt[dst[i]], 1);
}

__global__ void k_scan1(int n) {
    __shared__ int wsum[16];
    int b = blockIdx.x;
    int i = b * SCAN_CHUNK + threadIdx.x;
    int v = (i < n) ? g_cnt[i] : 0;
    for (int o = 16; o > 0; o >>= 1) v += __shfl_down_sync(~0u, v, o);
    int lane = threadIdx.x & 31, wid = threadIdx.x >> 5;
    if (lane == 0) wsum[wid] = v;
    __syncthreads();
    if (wid == 0) {
        int s = (lane < (SCAN_CHUNK / 32)) ? wsum[lane] : 0;
        for (int o = 16; o > 0; o >>= 1) s += __shfl_down_sync(~0u, s, o);
        if (lane == 0) g_bsum[b] = s;
    }
}

// fused: every block re-scans all block sums locally, then does its own chunk
__global__ void k_scan3(int n, int nblk) {
    __shared__ int wsum[16];
    __shared__ int sh_off;
    int b = blockIdx.x;
    int t = threadIdx.x;
    int lane = t & 31, wid = t >> 5;

    {
        int v = (t < nblk) ? g_bsum[t] : 0;
        int x = v;
        for (int o = 1; o < 32; o <<= 1) {
            int y = __shfl_up_sync(~0u, x, o);
            if (lane >= o) x += y;
        }
        if (lane == 31) wsum[wid] = x;
        __syncthreads();
        if (wid == 0) {
            int w = (lane < 16) ? wsum[lane] : 0;
            for (int o = 1; o < 16; o <<= 1) {
                int y = __shfl_up_sync(~0u, w, o);
                if (lane >= o) w += y;
            }
            if (lane < 16) wsum[lane] = w;
        }
        __syncthreads();
        int excl = x - v + (wid ? wsum[wid - 1] : 0);
        if (t == b) sh_off = excl;
        __syncthreads();
    }

    int i = b * SCAN_CHUNK + t;
    int v = (i < n) ? g_cnt[i] : 0;
    int x = v;
    for (int o = 1; o < 32; o <<= 1) {
        int y = __shfl_up_sync(~0u, x, o);
        if (lane >= o) x += y;
    }
    if (lane == 31) wsum[wid] = x;
    __syncthreads();
    if (wid == 0) {
        int w = (lane < 16) ? wsum[lane] : 0;
        for (int o = 1; o < 16; o <<= 1) {
            int y = __shfl_up_sync(~0u, w, o);
            if (lane >= o) w += y;
        }
        if (lane < 16) wsum[lane] = w;
    }
    __syncthreads();
    int excl = x - v + (wid ? wsum[wid - 1] : 0);
    if (i < n) {
        int s = excl + sh_off;
        g_start[i] = s;
        g_cursor[i] = s;
    }
}

__global__ void k_fill(const int* __restrict__ src, const int* __restrict__ dst,
                       int e) {
    int i = blockIdx.x * blockDim.x + threadIdx.x;
    if (i < e) {
        int p = atomicAdd(&g_cursor[dst[i]], 1);
        g_esrc[p] = src[i];
    }
}

// ---------------------------------------------------------------------------
__device__ __forceinline__ unsigned cvt_tf32(float f) {
    unsigned u;
    asm("cvt.rna.tf32.f32 %0, %1;" : "=r"(u) : "f"(f));
    return u;
}

// One-time: convert W into fragment-ordered tf32.
__global__ void k_wprep(const float* __restrict__ W) {
    int i = blockIdx.x * blockDim.x + threadIdx.x;
    if (i >= 16 * 8 * 32) return;
    int lane = i & 31;
    int ktp = (i >> 5) & 7;
    int nt = i >> 8;
    int g = lane >> 2, t = lane & 3;
    int nc = nt * 8 + g;
    int k0 = ktp * 16 + t;
    float4 o;
    o.x = __uint_as_float(cvt_tf32(W[(k0)      * F + nc]));
    o.y = __uint_as_float(cvt_tf32(W[(k0 + 4)  * F + nc]));
    o.z = __uint_as_float(cvt_tf32(W[(k0 + 8)  * F + nc]));
    o.w = __uint_as_float(cvt_tf32(W[(k0 + 12) * F + nc]));
    g_wfrag[i] = o;
}

// GEMM via HMMA tf32: g_hs = (x @ W) * dinv[row]. B frags streamed from
// g_wfrag (L1/L2-broadcast LDG.128). smem = x tile only -> 2 CTAs/SM.
__global__ __launch_bounds__(256, 2) void k_gemm(const float* __restrict__ x,
                                                 int n) {
    extern __shared__ float xs[];     // xs[r*PITCH + k] = tf32(x[row0+r][k])

    const int tid = threadIdx.x;
    const int row0 = blockIdx.x * 128;
    for (int i = tid; i < 128 * 32; i += 256) {
        int r = i >> 5, k4 = i & 31;
        float4 v = make_float4(0.f, 0.f, 0.f, 0.f);
        if (row0 + r < n) v = ((const float4*)x)[(long long)(row0 + r) * 32 + k4];
        v.x = __uint_as_float(cvt_tf32(v.x));
        v.y = __uint_as_float(cvt_tf32(v.y));
        v.z = __uint_as_float(cvt_tf32(v.z));
        v.w = __uint_as_float(cvt_tf32(v.w));
        *(float4*)&xs[r * PITCH + k4 * 4] = v;
    }
    // dinv for this block's rows
    if (tid < 128 && row0 + tid < n)
        g_dinv[row0 + tid] = rsqrtf((float)(g_cnt[row0 + tid] + 1));
    __syncthreads();

    const int warp = tid >> 5, lane = tid & 31;
    const int g = lane >> 2, t = lane & 3;
    const int rbase = warp * 16;

    unsigned a[16][4];
#pragma unroll
    for (int kt = 0; kt < 16; kt++) {
        a[kt][0] = __float_as_uint(xs[(rbase + g) * PITCH + kt * 8 + t]);
        a[kt][1] = __float_as_uint(xs[(rbase + g + 8) * PITCH + kt * 8 + t]);
        a[kt][2] = __float_as_uint(xs[(rbase + g) * PITCH + kt * 8 + t + 4]);
        a[kt][3] = __float_as_uint(xs[(rbase + g + 8) * PITCH + kt * 8 + t + 4]);
    }

    const int row_g = row0 + rbase + g;
    float sr  = (row_g < n)     ? rsqrtf((float)(g_cnt[row_g] + 1))     : 0.f;
    float sr8 = (row_g + 8 < n) ? rsqrtf((float)(g_cnt[row_g + 8] + 1)) : 0.f;

    const float4* wf = g_wfrag;
#pragma unroll 4
    for (int nt = 0; nt < 16; nt++) {
        float d0 = 0.f, d1 = 0.f, d2 = 0.f, d3 = 0.f;
#pragma unroll
        for (int ktp = 0; ktp < 8; ktp++) {
            float4 bf = wf[(nt * 8 + ktp) * 32 + lane];
            asm volatile(
                "mma.sync.aligned.m16n8k8.row.col.f32.tf32.tf32.f32 "
                "{%0,%1,%2,%3}, {%4,%5,%6,%7}, {%8,%9}, {%0,%1,%2,%3};"
                : "+f"(d0), "+f"(d1), "+f"(d2), "+f"(d3)
                : "r"(a[2 * ktp][0]), "r"(a[2 * ktp][1]),
                  "r"(a[2 * ktp][2]), "r"(a[2 * ktp][3]),
                  "r"(__float_as_uint(bf.x)), "r"(__float_as_uint(bf.y)));
            asm volatile(
                "mma.sync.aligned.m16n8k8.row.col.f32.tf32.tf32.f32 "
                "{%0,%1,%2,%3}, {%4,%5,%6,%7}, {%8,%9}, {%0,%1,%2,%3};"
                : "+f"(d0), "+f"(d1), "+f"(d2), "+f"(d3)
                : "r"(a[2 * ktp + 1][0]), "r"(a[2 * ktp + 1][1]),
                  "r"(a[2 * ktp + 1][2]), "r"(a[2 * ktp + 1][3]),
                  "r"(__float_as_uint(bf.z)), "r"(__float_as_uint(bf.w)));
        }
        if (row_g < n)
            *(float2*)&g_hs[(size_t)row_g * F + nt * 8 + t * 2] =
                make_float2(d0 * sr, d1 * sr);
        if (row_g + 8 < n)
            *(float2*)&g_hs[(size_t)(row_g + 8) * F + nt * 8 + t * 2] =
                make_float2(d2 * sr8, d3 * sr8);
    }
}

// ---------------------------------------------------------------------------
// Aggregate: one warp per dst node; float4/lane gathers, f32x2 accumulation.
// Unroll 8: eight independent row-gathers in flight per iteration.
__global__ __launch_bounds__(256) void k_agg(const float* __restrict__ bias,
                                             float* __restrict__ out, int n) {
    int node = blockIdx.x * 8 + (threadIdx.x >> 5);
    if (node >= n) return;
    int lane = threadIdx.x & 31;

    const float4* h = (const float4*)g_hs;
    float dd = g_dinv[node];

    unsigned long long p0, p1;
    {
        float4 sv = h[(size_t)node * 32 + lane];   // self-loop message
        asm("mov.b64 %0, {%1, %2};" : "=l"(p0) : "f"(sv.x), "f"(sv.y));
        asm("mov.b64 %0, {%1, %2};" : "=l"(p1) : "f"(sv.z), "f"(sv.w));
    }

    int j = g_start[node];
    int end = j + g_cnt[node];

    for (; j + 7 < end; j += 8) {
        int s0 = g_esrc[j],     s1 = g_esrc[j + 1];
        int s2 = g_esrc[j + 2], s3 = g_esrc[j + 3];
        int s4 = g_esrc[j + 4], s5 = g_esrc[j + 5];
        int s6 = g_esrc[j + 6], s7 = g_esrc[j + 7];
        float4 v0 = h[(size_t)s0 * 32 + lane];
        float4 v1 = h[(size_t)s1 * 32 + lane];
        float4 v2 = h[(size_t)s2 * 32 + lane];
        float4 v3 = h[(size_t)s3 * 32 + lane];
        float4 v4 = h[(size_t)s4 * 32 + lane];
        float4 v5 = h[(size_t)s5 * 32 + lane];
        float4 v6 = h[(size_t)s6 * 32 + lane];
        float4 v7 = h[(size_t)s7 * 32 + lane];
        unsigned long long q;
#pragma unroll
        for (int k = 0; k < 8; k++) {
            float4 v = (k == 0) ? v0 : (k == 1) ? v1 : (k == 2) ? v2 :
                       (k == 3) ? v3 : (k == 4) ? v4 : (k == 5) ? v5 :
                       (k == 6) ? v6 : v7;
            asm("mov.b64 %0, {%1, %2};" : "=l"(q) : "f"(v.x), "f"(v.y));
            asm("add.rn.f32x2 %0, %0, %1;" : "+l"(p0) : "l"(q));
            asm("mov.b64 %0, {%1, %2};" : "=l"(q) : "f"(v.z), "f"(v.w));
            asm("add.rn.f32x2 %0, %0, %1;" : "+l"(p1) : "l"(q));
        }
    }
    for (; j + 3 < end; j += 4) {
        int s0 = g_esrc[j],     s1 = g_esrc[j + 1];
        int s2 = g_esrc[j + 2], s3 = g_esrc[j + 3];
        float4 v0 = h[(size_t)s0 * 32 + lane];
        float4 v1 = h[(size_t)s1 * 32 + lane];
        float4 v2 = h[(size_t)s2 * 32 + lane];
        float4 v3 = h[(size_t)s3 * 32 + lane];
        unsigned long long q;
#pragma unroll
        for (int k = 0; k < 4; k++) {
            float4 v = (k == 0) ? v0 : (k == 1) ? v1 : (k == 2) ? v2 : v3;
            asm("mov.b64 %0, {%1, %2};" : "=l"(q) : "f"(v.x), "f"(v.y));
            asm("add.rn.f32x2 %0, %0, %1;" : "+l"(p0) : "l"(q));
            asm("mov.b64 %0, {%1, %2};" : "=l"(q) : "f"(v.z), "f"(v.w));
            asm("add.rn.f32x2 %0, %0, %1;" : "+l"(p1) : "l"(q));
        }
    }
    for (; j < end; j++) {
        int s = g_esrc[j];
        float4 v = h[(size_t)s * 32 + lane];
        unsigned long long q;
        asm("mov.b64 %0, {%1, %2};" : "=l"(q) : "f"(v.x), "f"(v.y));
        asm("add.rn.f32x2 %0, %0, %1;" : "+l"(p0) : "l"(q));
        asm("mov.b64 %0, {%1, %2};" : "=l"(q) : "f"(v.z), "f"(v.w));
        asm("add.rn.f32x2 %0, %0, %1;" : "+l"(p1) : "l"(q));
    }

    float a0, a1, a2, a3;
    asm("mov.b64 {%0, %1}, %2;" : "=f"(a0), "=f"(a1) : "l"(p0));
    asm("mov.b64 {%0, %1}, %2;" : "=f"(a2), "=f"(a3) : "l"(p1));

    float4 bv = ((const float4*)bias)[lane];
    float4 o;
    o.x = a0 * dd + bv.x;
    o.y = a1 * dd + bv.y;
    o.z = a2 * dd + bv.z;
    o.w = a3 * dd + bv.w;
    ((float4*)out)[(size_t)node * 32 + lane] = o;
}

// ---------------------------------------------------------------------------
extern "C" void kernel_launch(void* const* d_in, const int* in_sizes, int n_in,
                              void* d_out, int out_size) {
    const float* x  = (const float*)d_in[0];
    const int*   ei = (const int*)d_in[1];
    const float* W  = (const float*)d_in[3];
    const float* b  = (const float*)d_in[4];
    float* out = (float*)d_out;

    int n = in_sizes[0] / F;
    int e = in_sizes[1] / 2;
    const int* src = ei;
    const int* dst = ei + e;

    int nblk = (n + SCAN_CHUNK - 1) / SCAN_CHUNK;

    static bool attr_done = false;
    int smem = 128 * PITCH * (int)sizeof(float);   // 67.6 KB
    if (!attr_done) {
        cudaFuncSetAttribute(k_gemm, cudaFuncAttributeMaxDynamicSharedMemorySize,
                             smem);
        attr_done = true;
    }

    k_zero <<<(n + 255) / 256, 256>>>(n);                  // 1
    k_hist <<<(e + 255) / 256, 256>>>(dst, e);             // 2
    k_wprep<<<16, 256>>>(W);                               // 3
    k_gemm <<<(n + 127) / 128, 256, smem>>>(x, n);         // 4  <- profiled slot
    k_scan1<<<nblk, SCAN_CHUNK>>>(n);                      // 5
    k_scan3<<<nblk, SCAN_CHUNK>>>(n, nblk);                // 6
    k_fill <<<(e + 255) / 256, 256>>>(src, dst, e);        // 7
    k_agg  <<<(n + 7) / 8, 256>>>(b, out, n);              // 8
}

// round 11
// speedup vs baseline: 1.7868x; 1.1038x over previous
#include <cuda_runtime.h>
#include <cuda_fp16.h>
#include <cstdint>

#define MAX_N 100000
#define MAX_E 1600000
#define F 128
#define SCAN_CHUNK 512
#define MAX_BLK ((MAX_N + SCAN_CHUNK - 1) / SCAN_CHUNK)
#define PITCH 132   // 128 + 4 pad: conflict-free mma A-frag loads

// Scratch (__device__ globals; no allocations allowed)
__device__ float g_hs[(size_t)MAX_N * F];   // (x@W)*dinv[row], fp32 (51.2MB)
__device__ float g_dinv[MAX_N];
__device__ int   g_cnt[MAX_N];
__device__ int   g_start[MAX_N];
__device__ int   g_cursor[MAX_N];
__device__ int   g_esrc[MAX_E];
__device__ int   g_bsum[MAX_BLK];
__device__ float4 g_wfrag[16 * 8 * 32];     // frag-ordered tf32 W (64KB)

// ---------------------------------------------------------------------------
__global__ void k_zero(int n) {
    int i = blockIdx.x * blockDim.x + threadIdx.x;
    if (i < n) g_cnt[i] = 0;
}

__global__ void k_hist(const int* __restrict__ dst, int e) {
    int i = blockIdx.x * blockDim.x + threadIdx.x;
    if (i < e) atomicAdd(&g_cnt[dst[i]], 1);
}

__global__ void k_scan1(int n) {
    __shared__ int wsum[16];
    int b = blockIdx.x;
    int i = b * SCAN_CHUNK + threadIdx.x;
    int v = (i < n) ? g_cnt[i] : 0;
    for (int o = 16; o > 0; o >>= 1) v += __shfl_down_sync(~0u, v, o);
    int lane = threadIdx.x & 31, wid = threadIdx.x >> 5;
    if (lane == 0) wsum[wid] = v;
    __syncthreads();
    if (wid == 0) {
        int s = (lane < (SCAN_CHUNK / 32)) ? wsum[lane] : 0;
        for (int o = 16; o > 0; o >>= 1) s += __shfl_down_sync(~0u, s, o);
        if (lane == 0) g_bsum[b] = s;
    }
}

// fused: every block re-scans all block sums locally, then does its own chunk
__global__ void k_scan3(int n, int nblk) {
    __shared__ int wsum[16];
    __shared__ int sh_off;
    int b = blockIdx.x;
    int t = threadIdx.x;
    int lane = t & 31, wid = t >> 5;

    {
        int v = (t < nblk) ? g_bsum[t] : 0;
        int x = v;
        for (int o = 1; o < 32; o <<= 1) {
            int y = __shfl_up_sync(~0u, x, o);
            if (lane >= o) x += y;
        }
        if (lane == 31) wsum[wid] = x;
        __syncthreads();
        if (wid == 0) {
            int w = (lane < 16) ? wsum[lane] : 0;
            for (int o = 1; o < 16; o <<= 1) {
                int y = __shfl_up_sync(~0u, w, o);
                if (lane >= o) w += y;
            }
            if (lane < 16) wsum[lane] = w;
        }
        __syncthreads();
        int excl = x - v + (wid ? wsum[wid - 1] : 0);
        if (t == b) sh_off = excl;
        __syncthreads();
    }

    int i = b * SCAN_CHUNK + t;
    int v = (i < n) ? g_cnt[i] : 0;
    int x = v;
    for (int o = 1; o < 32; o <<= 1) {
        int y = __shfl_up_sync(~0u, x, o);
        if (lane >= o) x += y;
    }
    if (lane == 31) wsum[wid] = x;
    __syncthreads();
    if (wid == 0) {
        int w = (lane < 16) ? wsum[lane] : 0;
        for (int o = 1; o < 16; o <<= 1) {
            int y = __shfl_up_sync(~0u, w, o);
            if (lane >= o) w += y;
        }
        if (lane < 16) wsum[lane] = w;
    }
    __syncthreads();
    int excl = x - v + (wid ? wsum[wid - 1] : 0);
    if (i < n) {
        int s = excl + sh_off;
        g_start[i] = s;
        g_cursor[i] = s;
    }
}

__global__ void k_fill(const int* __restrict__ src, const int* __restrict__ dst,
                       int e) {
    int i = blockIdx.x * blockDim.x + threadIdx.x;
    if (i < e) {
        int p = atomicAdd(&g_cursor[dst[i]], 1);
        g_esrc[p] = src[i];
    }
}

// ---------------------------------------------------------------------------
__device__ __forceinline__ unsigned cvt_tf32(float f) {
    unsigned u;
    asm("cvt.rna.tf32.f32 %0, %1;" : "=r"(u) : "f"(f));
    return u;
}

// One-time: convert W into fragment-ordered tf32.
__global__ void k_wprep(const float* __restrict__ W) {
    int i = blockIdx.x * blockDim.x + threadIdx.x;
    if (i >= 16 * 8 * 32) return;
    int lane = i & 31;
    int ktp = (i >> 5) & 7;
    int nt = i >> 8;
    int g = lane >> 2, t = lane & 3;
    int nc = nt * 8 + g;
    int k0 = ktp * 16 + t;
    float4 o;
    o.x = __uint_as_float(cvt_tf32(W[(k0)      * F + nc]));
    o.y = __uint_as_float(cvt_tf32(W[(k0 + 4)  * F + nc]));
    o.z = __uint_as_float(cvt_tf32(W[(k0 + 8)  * F + nc]));
    o.w = __uint_as_float(cvt_tf32(W[(k0 + 12) * F + nc]));
    g_wfrag[i] = o;
}

// GEMM via HMMA tf32: g_hs = (x @ W) * dinv[row]. B frags streamed from
// g_wfrag (L1/L2-broadcast LDG.128). smem = x tile only -> 2 CTAs/SM.
__global__ __launch_bounds__(256, 2) void k_gemm(const float* __restrict__ x,
                                                 int n) {
    extern __shared__ float xs[];     // xs[r*PITCH + k] = tf32(x[row0+r][k])

    const int tid = threadIdx.x;
    const int row0 = blockIdx.x * 128;
    for (int i = tid; i < 128 * 32; i += 256) {
        int r = i >> 5, k4 = i & 31;
        float4 v = make_float4(0.f, 0.f, 0.f, 0.f);
        if (row0 + r < n) v = ((const float4*)x)[(long long)(row0 + r) * 32 + k4];
        v.x = __uint_as_float(cvt_tf32(v.x));
        v.y = __uint_as_float(cvt_tf32(v.y));
        v.z = __uint_as_float(cvt_tf32(v.z));
        v.w = __uint_as_float(cvt_tf32(v.w));
        *(float4*)&xs[r * PITCH + k4 * 4] = v;
    }
    // dinv for this block's rows
    if (tid < 128 && row0 + tid < n)
        g_dinv[row0 + tid] = rsqrtf((float)(g_cnt[row0 + tid] + 1));
    __syncthreads();

    const int warp = tid >> 5, lane = tid & 31;
    const int g = lane >> 2, t = lane & 3;
    const int rbase = warp * 16;

    unsigned a[16][4];
#pragma unroll
    for (int kt = 0; kt < 16; kt++) {
        a[kt][0] = __float_as_uint(xs[(rbase + g) * PITCH + kt * 8 + t]);
        a[kt][1] = __float_as_uint(xs[(rbase + g + 8) * PITCH + kt * 8 + t]);
        a[kt][2] = __float_as_uint(xs[(rbase + g) * PITCH + kt * 8 + t + 4]);
        a[kt][3] = __float_as_uint(xs[(rbase + g + 8) * PITCH + kt * 8 + t + 4]);
    }

    const int row_g = row0 + rbase + g;
    float sr  = (row_g < n)     ? rsqrtf((float)(g_cnt[row_g] + 1))     : 0.f;
    float sr8 = (row_g + 8 < n) ? rsqrtf((float)(g_cnt[row_g + 8] + 1)) : 0.f;

    const float4* wf = g_wfrag;
#pragma unroll 4
    for (int nt = 0; nt < 16; nt++) {
        float d0 = 0.f, d1 = 0.f, d2 = 0.f, d3 = 0.f;
#pragma unroll
        for (int ktp = 0; ktp < 8; ktp++) {
            float4 bf = wf[(nt * 8 + ktp) * 32 + lane];
            asm volatile(
                "mma.sync.aligned.m16n8k8.row.col.f32.tf32.tf32.f32 "
                "{%0,%1,%2,%3}, {%4,%5,%6,%7}, {%8,%9}, {%0,%1,%2,%3};"
                : "+f"(d0), "+f"(d1), "+f"(d2), "+f"(d3)
                : "r"(a[2 * ktp][0]), "r"(a[2 * ktp][1]),
                  "r"(a[2 * ktp][2]), "r"(a[2 * ktp][3]),
                  "r"(__float_as_uint(bf.x)), "r"(__float_as_uint(bf.y)));
            asm volatile(
                "mma.sync.aligned.m16n8k8.row.col.f32.tf32.tf32.f32 "
                "{%0,%1,%2,%3}, {%4,%5,%6,%7}, {%8,%9}, {%0,%1,%2,%3};"
                : "+f"(d0), "+f"(d1), "+f"(d2), "+f"(d3)
                : "r"(a[2 * ktp + 1][0]), "r"(a[2 * ktp + 1][1]),
                  "r"(a[2 * ktp + 1][2]), "r"(a[2 * ktp + 1][3]),
                  "r"(__float_as_uint(bf.z)), "r"(__float_as_uint(bf.w)));
        }
        if (row_g < n)
            *(float2*)&g_hs[(size_t)row_g * F + nt * 8 + t * 2] =
                make_float2(d0 * sr, d1 * sr);
        if (row_g + 8 < n)
            *(float2*)&g_hs[(size_t)(row_g + 8) * F + nt * 8 + t * 2] =
                make_float2(d2 * sr8, d3 * sr8);
    }
}

// ---------------------------------------------------------------------------
// Aggregate: one warp per dst node; float4/lane gathers, f32x2 accumulation.
__global__ __launch_bounds__(256) void k_agg(const float* __restrict__ bias,
                                             float* __restrict__ out, int n) {
    int node = blockIdx.x * 8 + (threadIdx.x >> 5);
    if (node >= n) return;
    int lane = threadIdx.x & 31;

    const float4* h = (const float4*)g_hs;
    float dd = g_dinv[node];

    unsigned long long p0, p1;
    {
        float4 sv = h[(size_t)node * 32 + lane];   // self-loop message
        asm("mov.b64 %0, {%1, %2};" : "=l"(p0) : "f"(sv.x), "f"(sv.y));
        asm("mov.b64 %0, {%1, %2};" : "=l"(p1) : "f"(sv.z), "f"(sv.w));
    }

    int j = g_start[node];
    int end = j + g_cnt[node];

    for (; j + 7 < end; j += 8) {
        int s0 = g_esrc[j],     s1 = g_esrc[j + 1];
        int s2 = g_esrc[j + 2], s3 = g_esrc[j + 3];
        int s4 = g_esrc[j + 4], s5 = g_esrc[j + 5];
        int s6 = g_esrc[j + 6], s7 = g_esrc[j + 7];
        float4 v0 = h[(size_t)s0 * 32 + lane];
        float4 v1 = h[(size_t)s1 * 32 + lane];
        float4 v2 = h[(size_t)s2 * 32 + lane];
        float4 v3 = h[(size_t)s3 * 32 + lane];
        float4 v4 = h[(size_t)s4 * 32 + lane];
        float4 v5 = h[(size_t)s5 * 32 + lane];
        float4 v6 = h[(size_t)s6 * 32 + lane];
        float4 v7 = h[(size_t)s7 * 32 + lane];
        unsigned long long q;
#pragma unroll
        for (int k = 0; k < 8; k++) {
            float4 v = (k == 0) ? v0 : (k == 1) ? v1 : (k == 2) ? v2 :
                       (k == 3) ? v3 : (k == 4) ? v4 : (k == 5) ? v5 :
                       (k == 6) ? v6 : v7;
            asm("mov.b64 %0, {%1, %2};" : "=l"(q) : "f"(v.x), "f"(v.y));
            asm("add.rn.f32x2 %0, %0, %1;" : "+l"(p0) : "l"(q));
            asm("mov.b64 %0, {%1, %2};" : "=l"(q) : "f"(v.z), "f"(v.w));
            asm("add.rn.f32x2 %0, %0, %1;" : "+l"(p1) : "l"(q));
        }
    }
    for (; j + 3 < end; j += 4) {
        int s0 = g_esrc[j],     s1 = g_esrc[j + 1];
        int s2 = g_esrc[j + 2], s3 = g_esrc[j + 3];
        float4 v0 = h[(size_t)s0 * 32 + lane];
        float4 v1 = h[(size_t)s1 * 32 + lane];
        float4 v2 = h[(size_t)s2 * 32 + lane];
        float4 v3 = h[(size_t)s3 * 32 + lane];
        unsigned long long q;
#pragma unroll
        for (int k = 0; k < 4; k++) {
            float4 v = (k == 0) ? v0 : (k == 1) ? v1 : (k == 2) ? v2 : v3;
            asm("mov.b64 %0, {%1, %2};" : "=l"(q) : "f"(v.x), "f"(v.y));
            asm("add.rn.f32x2 %0, %0, %1;" : "+l"(p0) : "l"(q));
            asm("mov.b64 %0, {%1, %2};" : "=l"(q) : "f"(v.z), "f"(v.w));
            asm("add.rn.f32x2 %0, %0, %1;" : "+l"(p1) : "l"(q));
        }
    }
    for (; j < end; j++) {
        int s = g_esrc[j];
        float4 v = h[(size_t)s * 32 + lane];
        unsigned long long q;
        asm("mov.b64 %0, {%1, %2};" : "=l"(q) : "f"(v.x), "f"(v.y));
        asm("add.rn.f32x2 %0, %0, %1;" : "+l"(p0) : "l"(q));
        asm("mov.b64 %0, {%1, %2};" : "=l"(q) : "f"(v.z), "f"(v.w));
        asm("add.rn.f32x2 %0, %0, %1;" : "+l"(p1) : "l"(q));
    }

    float a0, a1, a2, a3;
    asm("mov.b64 {%0, %1}, %2;" : "=f"(a0), "=f"(a1) : "l"(p0));
    asm("mov.b64 {%0, %1}, %2;" : "=f"(a2), "=f"(a3) : "l"(p1));

    float4 bv = ((const float4*)bias)[lane];
    float4 o;
    o.x = a0 * dd + bv.x;
    o.y = a1 * dd + bv.y;
    o.z = a2 * dd + bv.z;
    o.w = a3 * dd + bv.w;
    ((float4*)out)[(size_t)node * 32 + lane] = o;
}

// ---------------------------------------------------------------------------
// Launch DAG (fork-join for graph-level concurrency):
//   zero -> hist -> [A: scan1 -> scan3 -> fill]   (edge chain, ~18us)
//                   [B: wprep -> gemm]            (dense chain, ~60us, side stream)
//   join(A, B) -> agg
extern "C" void kernel_launch(void* const* d_in, const int* in_sizes, int n_in,
                              void* d_out, int out_size) {
    const float* x  = (const float*)d_in[0];
    const int*   ei = (const int*)d_in[1];
    const float* W  = (const float*)d_in[3];
    const float* b  = (const float*)d_in[4];
    float* out = (float*)d_out;

    int n = in_sizes[0] / F;
    int e = in_sizes[1] / 2;
    const int* src = ei;
    const int* dst = ei + e;

    int nblk = (n + SCAN_CHUNK - 1) / SCAN_CHUNK;
    int smem = 128 * PITCH * (int)sizeof(float);   // 67.6 KB

    // One-time host-side setup on the (uncaptured) correctness call.
    static cudaStream_t s2 = nullptr;
    static cudaEvent_t evHist = nullptr, evGemm = nullptr;
    if (s2 == nullptr) {
        cudaFuncSetAttribute(k_gemm, cudaFuncAttributeMaxDynamicSharedMemorySize,
                             smem);
        cudaStreamCreateWithFlags(&s2, cudaStreamNonBlocking);
        cudaEventCreateWithFlags(&evHist, cudaEventDisableTiming);
        cudaEventCreateWithFlags(&evGemm, cudaEventDisableTiming);
    }

    k_zero <<<(n + 255) / 256, 256>>>(n);
    k_hist <<<(e + 255) / 256, 256>>>(dst, e);
    cudaEventRecord(evHist, 0);

    // dense chain on side stream (waits for hist: gemm reads g_cnt for dinv)
    cudaStreamWaitEvent(s2, evHist, 0);
    k_wprep<<<16, 256, 0, s2>>>(W);
    k_gemm <<<(n + 127) / 128, 256, smem, s2>>>(x, n);
    cudaEventRecord(evGemm, s2);

    // edge chain on main stream (overlaps with gemm)
    k_scan1<<<nblk, SCAN_CHUNK>>>(n);
    k_scan3<<<nblk, SCAN_CHUNK>>>(n, nblk);
    k_fill <<<(e + 255) / 256, 256>>>(src, dst, e);

    // join
    cudaStreamWaitEvent(0, evGemm, 0);
    k_agg  <<<(n + 7) / 8, 256>>>(b, out, n);
}

// round 12
// speedup vs baseline: 1.9391x; 1.0852x over previous
#include <cuda_runtime.h>
#include <cuda_fp16.h>
#include <cstdint>

#define MAX_N 100000
#define MAX_E 1600000
#define F 128
#define SCAN_CHUNK 512
#define MAX_BLK ((MAX_N + SCAN_CHUNK - 1) / SCAN_CHUNK)
#define PITCH 132   // 128 + 4 pad: conflict-free mma A-frag loads

// Scratch (__device__ globals; no allocations allowed)
__device__ __half2 g_h16[(size_t)MAX_N * (F / 2)];  // (x@W)*dinv[row], fp16
__device__ float g_dinv[MAX_N];
__device__ int   g_cnt[MAX_N];
__device__ int   g_start[MAX_N];
__device__ int   g_cursor[MAX_N];
__device__ int   g_esrc[MAX_E];
__device__ int   g_bsum[MAX_BLK];
__device__ float4 g_wfrag[16 * 8 * 32];     // frag-ordered tf32 W (64KB)

// ---------------------------------------------------------------------------
__global__ void k_zero(int n) {
    int i = blockIdx.x * blockDim.x + threadIdx.x;
    if (i < n) g_cnt[i] = 0;
}

__global__ void k_hist(const int* __restrict__ dst, int e) {
    int i = blockIdx.x * blockDim.x + threadIdx.x;
    if (i < e) atomicAdd(&g_cnt[dst[i]], 1);
}

__global__ void k_scan1(int n) {
    __shared__ int wsum[16];
    int b = blockIdx.x;
    int i = b * SCAN_CHUNK + threadIdx.x;
    int v = (i < n) ? g_cnt[i] : 0;
    for (int o = 16; o > 0; o >>= 1) v += __shfl_down_sync(~0u, v, o);
    int lane = threadIdx.x & 31, wid = threadIdx.x >> 5;
    if (lane == 0) wsum[wid] = v;
    __syncthreads();
    if (wid == 0) {
        int s = (lane < (SCAN_CHUNK / 32)) ? wsum[lane] : 0;
        for (int o = 16; o > 0; o >>= 1) s += __shfl_down_sync(~0u, s, o);
        if (lane == 0) g_bsum[b] = s;
    }
}

// fused: every block re-scans all block sums locally, then does its own chunk
__global__ void k_scan3(int n, int nblk) {
    __shared__ int wsum[16];
    __shared__ int sh_off;
    int b = blockIdx.x;
    int t = threadIdx.x;
    int lane = t & 31, wid = t >> 5;

    {
        int v = (t < nblk) ? g_bsum[t] : 0;
        int x = v;
        for (int o = 1; o < 32; o <<= 1) {
            int y = __shfl_up_sync(~0u, x, o);
            if (lane >= o) x += y;
        }
        if (lane == 31) wsum[wid] = x;
        __syncthreads();
        if (wid == 0) {
            int w = (lane < 16) ? wsum[lane] : 0;
            for (int o = 1; o < 16; o <<= 1) {
                int y = __shfl_up_sync(~0u, w, o);
                if (lane >= o) w += y;
            }
            if (lane < 16) wsum[lane] = w;
        }
        __syncthreads();
        int excl = x - v + (wid ? wsum[wid - 1] : 0);
        if (t == b) sh_off = excl;
        __syncthreads();
    }

    int i = b * SCAN_CHUNK + t;
    int v = (i < n) ? g_cnt[i] : 0;
    int x = v;
    for (int o = 1; o < 32; o <<= 1) {
        int y = __shfl_up_sync(~0u, x, o);
        if (lane >= o) x += y;
    }
    if (lane == 31) wsum[wid] = x;
    __syncthreads();
    if (wid == 0) {
        int w = (lane < 16) ? wsum[lane] : 0;
        for (int o = 1; o < 16; o <<= 1) {
            int y = __shfl_up_sync(~0u, w, o);
            if (lane >= o) w += y;
        }
        if (lane < 16) wsum[lane] = w;
    }
    __syncthreads();
    int excl = x - v + (wid ? wsum[wid - 1] : 0);
    if (i < n) {
        int s = excl + sh_off;
        g_start[i] = s;
        g_cursor[i] = s;
    }
}

__global__ void k_fill(const int* __restrict__ src, const int* __restrict__ dst,
                       int e) {
    int i = blockIdx.x * blockDim.x + threadIdx.x;
    if (i < e) {
        int p = atomicAdd(&g_cursor[dst[i]], 1);
        g_esrc[p] = src[i];
    }
}

// ---------------------------------------------------------------------------
__device__ __forceinline__ unsigned cvt_tf32(float f) {
    unsigned u;
    asm("cvt.rna.tf32.f32 %0, %1;" : "=r"(u) : "f"(f));
    return u;
}

// One-time: convert W into fragment-ordered tf32.
__global__ void k_wprep(const float* __restrict__ W) {
    int i = blockIdx.x * blockDim.x + threadIdx.x;
    if (i >= 16 * 8 * 32) return;
    int lane = i & 31;
    int ktp = (i >> 5) & 7;
    int nt = i >> 8;
    int g = lane >> 2, t = lane & 3;
    int nc = nt * 8 + g;
    int k0 = ktp * 16 + t;
    float4 o;
    o.x = __uint_as_float(cvt_tf32(W[(k0)      * F + nc]));
    o.y = __uint_as_float(cvt_tf32(W[(k0 + 4)  * F + nc]));
    o.z = __uint_as_float(cvt_tf32(W[(k0 + 8)  * F + nc]));
    o.w = __uint_as_float(cvt_tf32(W[(k0 + 12) * F + nc]));
    g_wfrag[i] = o;
}

// GEMM via HMMA tf32: g_h16 = (x @ W) * dinv[row], fp16 out. B frags streamed
// from g_wfrag (L1/L2-broadcast LDG.128). smem = x tile only -> 2 CTAs/SM.
__global__ __launch_bounds__(256, 2) void k_gemm(const float* __restrict__ x,
                                                 int n) {
    extern __shared__ float xs[];     // xs[r*PITCH + k] = tf32(x[row0+r][k])

    const int tid = threadIdx.x;
    const int row0 = blockIdx.x * 128;
    for (int i = tid; i < 128 * 32; i += 256) {
        int r = i >> 5, k4 = i & 31;
        float4 v = make_float4(0.f, 0.f, 0.f, 0.f);
        if (row0 + r < n) v = ((const float4*)x)[(long long)(row0 + r) * 32 + k4];
        v.x = __uint_as_float(cvt_tf32(v.x));
        v.y = __uint_as_float(cvt_tf32(v.y));
        v.z = __uint_as_float(cvt_tf32(v.z));
        v.w = __uint_as_float(cvt_tf32(v.w));
        *(float4*)&xs[r * PITCH + k4 * 4] = v;
    }
    // dinv for this block's rows
    if (tid < 128 && row0 + tid < n)
        g_dinv[row0 + tid] = rsqrtf((float)(g_cnt[row0 + tid] + 1));
    __syncthreads();

    const int warp = tid >> 5, lane = tid & 31;
    const int g = lane >> 2, t = lane & 3;
    const int rbase = warp * 16;

    unsigned a[16][4];
#pragma unroll
    for (int kt = 0; kt < 16; kt++) {
        a[kt][0] = __float_as_uint(xs[(rbase + g) * PITCH + kt * 8 + t]);
        a[kt][1] = __float_as_uint(xs[(rbase + g + 8) * PITCH + kt * 8 + t]);
        a[kt][2] = __float_as_uint(xs[(rbase + g) * PITCH + kt * 8 + t + 4]);
        a[kt][3] = __float_as_uint(xs[(rbase + g + 8) * PITCH + kt * 8 + t + 4]);
    }

    const int row_g = row0 + rbase + g;
    float sr  = (row_g < n)     ? rsqrtf((float)(g_cnt[row_g] + 1))     : 0.f;
    float sr8 = (row_g + 8 < n) ? rsqrtf((float)(g_cnt[row_g + 8] + 1)) : 0.f;

    const float4* wf = g_wfrag;
#pragma unroll 4
    for (int nt = 0; nt < 16; nt++) {
        float d0 = 0.f, d1 = 0.f, d2 = 0.f, d3 = 0.f;
#pragma unroll
        for (int ktp = 0; ktp < 8; ktp++) {
            float4 bf = wf[(nt * 8 + ktp) * 32 + lane];
            asm volatile(
                "mma.sync.aligned.m16n8k8.row.col.f32.tf32.tf32.f32 "
                "{%0,%1,%2,%3}, {%4,%5,%6,%7}, {%8,%9}, {%0,%1,%2,%3};"
                : "+f"(d0), "+f"(d1), "+f"(d2), "+f"(d3)
                : "r"(a[2 * ktp][0]), "r"(a[2 * ktp][1]),
                  "r"(a[2 * ktp][2]), "r"(a[2 * ktp][3]),
                  "r"(__float_as_uint(bf.x)), "r"(__float_as_uint(bf.y)));
            asm volatile(
                "mma.sync.aligned.m16n8k8.row.col.f32.tf32.tf32.f32 "
                "{%0,%1,%2,%3}, {%4,%5,%6,%7}, {%8,%9}, {%0,%1,%2,%3};"
                : "+f"(d0), "+f"(d1), "+f"(d2), "+f"(d3)
                : "r"(a[2 * ktp + 1][0]), "r"(a[2 * ktp + 1][1]),
                  "r"(a[2 * ktp + 1][2]), "r"(a[2 * ktp + 1][3]),
                  "r"(__float_as_uint(bf.z)), "r"(__float_as_uint(bf.w)));
        }
        if (row_g < n)
            g_h16[(size_t)row_g * 64 + nt * 4 + t] =
                __floats2half2_rn(d0 * sr, d1 * sr);
        if (row_g + 8 < n)
            g_h16[(size_t)(row_g + 8) * 64 + nt * 4 + t] =
                __floats2half2_rn(d2 * sr8, d3 * sr8);
    }
}

// ---------------------------------------------------------------------------
// Aggregate: one warp per dst node; uint2/lane fp16 gathers (256B rows),
// fp32 accumulation, 8 independent gathers in flight per iteration.
__global__ __launch_bounds__(256) void k_agg(const float* __restrict__ bias,
                                             float* __restrict__ out, int n) {
    int node = blockIdx.x * 8 + (threadIdx.x >> 5);
    if (node >= n) return;
    int lane = threadIdx.x & 31;

    const uint2* h = (const uint2*)g_h16;  // 4 halfs / lane / row
    float dd = g_dinv[node];

    float4 acc;
    {
        uint2 sv = h[(size_t)node * 32 + lane];  // self-loop message
        float2 f0 = __half22float2(*(__half2*)&sv.x);
        float2 f1 = __half22float2(*(__half2*)&sv.y);
        acc.x = f0.x; acc.y = f0.y; acc.z = f1.x; acc.w = f1.y;
    }

    int j = g_start[node];
    int end = j + g_cnt[node];

    for (; j + 7 < end; j += 8) {
        int s0 = g_esrc[j],     s1 = g_esrc[j + 1];
        int s2 = g_esrc[j + 2], s3 = g_esrc[j + 3];
        int s4 = g_esrc[j + 4], s5 = g_esrc[j + 5];
        int s6 = g_esrc[j + 6], s7 = g_esrc[j + 7];
        uint2 v0 = h[(size_t)s0 * 32 + lane];
        uint2 v1 = h[(size_t)s1 * 32 + lane];
        uint2 v2 = h[(size_t)s2 * 32 + lane];
        uint2 v3 = h[(size_t)s3 * 32 + lane];
        uint2 v4 = h[(size_t)s4 * 32 + lane];
        uint2 v5 = h[(size_t)s5 * 32 + lane];
        uint2 v6 = h[(size_t)s6 * 32 + lane];
        uint2 v7 = h[(size_t)s7 * 32 + lane];
#pragma unroll
        for (int k = 0; k < 8; k++) {
            uint2 v = (k == 0) ? v0 : (k == 1) ? v1 : (k == 2) ? v2 :
                      (k == 3) ? v3 : (k == 4) ? v4 : (k == 5) ? v5 :
                      (k == 6) ? v6 : v7;
            float2 f0 = __half22float2(*(__half2*)&v.x);
            float2 f1 = __half22float2(*(__half2*)&v.y);
            acc.x += f0.x; acc.y += f0.y; acc.z += f1.x; acc.w += f1.y;
        }
    }
    for (; j + 3 < end; j += 4) {
        int s0 = g_esrc[j],     s1 = g_esrc[j + 1];
        int s2 = g_esrc[j + 2], s3 = g_esrc[j + 3];
        uint2 v0 = h[(size_t)s0 * 32 + lane];
        uint2 v1 = h[(size_t)s1 * 32 + lane];
        uint2 v2 = h[(size_t)s2 * 32 + lane];
        uint2 v3 = h[(size_t)s3 * 32 + lane];
#pragma unroll
        for (int k = 0; k < 4; k++) {
            uint2 v = (k == 0) ? v0 : (k == 1) ? v1 : (k == 2) ? v2 : v3;
            float2 f0 = __half22float2(*(__half2*)&v.x);
            float2 f1 = __half22float2(*(__half2*)&v.y);
            acc.x += f0.x; acc.y += f0.y; acc.z += f1.x; acc.w += f1.y;
        }
    }
    for (; j < end; j++) {
        int s = g_esrc[j];
        uint2 v = h[(size_t)s * 32 + lane];
        float2 f0 = __half22float2(*(__half2*)&v.x);
        float2 f1 = __half22float2(*(__half2*)&v.y);
        acc.x += f0.x; acc.y += f0.y; acc.z += f1.x; acc.w += f1.y;
    }

    float4 bv = ((const float4*)bias)[lane];
    float4 o;
    o.x = acc.x * dd + bv.x;
    o.y = acc.y * dd + bv.y;
    o.z = acc.z * dd + bv.z;
    o.w = acc.w * dd + bv.w;
    ((float4*)out)[(size_t)node * 32 + lane] = o;
}

// ---------------------------------------------------------------------------
// Launch DAG (fork-join for graph-level concurrency):
//   zero -> hist -> [A: scan1 -> scan3 -> fill]   (edge chain, ~18us)
//                   [B: wprep -> gemm]            (dense chain, ~60us, side stream)
//   join(A, B) -> agg
extern "C" void kernel_launch(void* const* d_in, const int* in_sizes, int n_in,
                              void* d_out, int out_size) {
    const float* x  = (const float*)d_in[0];
    const int*   ei = (const int*)d_in[1];
    const float* W  = (const float*)d_in[3];
    const float* b  = (const float*)d_in[4];
    float* out = (float*)d_out;

    int n = in_sizes[0] / F;
    int e = in_sizes[1] / 2;
    const int* src = ei;
    const int* dst = ei + e;

    int nblk = (n + SCAN_CHUNK - 1) / SCAN_CHUNK;
    int smem = 128 * PITCH * (int)sizeof(float);   // 67.6 KB

    // One-time host-side setup on the (uncaptured) correctness call.
    static cudaStream_t s2 = nullptr;
    static cudaEvent_t evHist = nullptr, evGemm = nullptr;
    if (s2 == nullptr) {
        cudaFuncSetAttribute(k_gemm, cudaFuncAttributeMaxDynamicSharedMemorySize,
                             smem);
        cudaStreamCreateWithFlags(&s2, cudaStreamNonBlocking);
        cudaEventCreateWithFlags(&evHist, cudaEventDisableTiming);
        cudaEventCreateWithFlags(&evGemm, cudaEventDisableTiming);
    }

    k_zero <<<(n + 255) / 256, 256>>>(n);
    k_hist <<<(e + 255) / 256, 256>>>(dst, e);
    cudaEventRecord(evHist, 0);

    // dense chain on side stream (waits for hist: gemm reads g_cnt for dinv)
    cudaStreamWaitEvent(s2, evHist, 0);
    k_wprep<<<16, 256, 0, s2>>>(W);
    k_gemm <<<(n + 127) / 128, 256, smem, s2>>>(x, n);
    cudaEventRecord(evGemm, s2);

    // edge chain on main stream (overlaps with gemm)
    k_scan1<<<nblk, SCAN_CHUNK>>>(n);
    k_scan3<<<nblk, SCAN_CHUNK>>>(n, nblk);
    k_fill <<<(e + 255) / 256, 256>>>(src, dst, e);

    // join
    cudaStreamWaitEvent(0, evGemm, 0);
    k_agg  <<<(n + 7) / 8, 256>>>(b, out, n);
}